// round 1
// baseline (speedup 1.0000x reference)
#include <cuda_runtime.h>
#include <math.h>

#define IN_F   512
#define OUT_F  128
#define MAX_N  50000
#define BN_EPS 1e-5f

// ---------------- static device scratch (no allocations allowed) -------------
__device__ float g_hamilton[IN_F * OUT_F];                 // 256 KB
__device__ float g_support[(long long)MAX_N * OUT_F];      // 25.6 MB
__device__ float g_colsum[OUT_F];
__device__ float g_colsumsq[OUT_F];
__device__ float g_scale[OUT_F];
__device__ float g_shift[OUT_F];

// Octonion block pattern: column-block j uses row-block list idx/sgn[j][i].
__constant__ int c_idx[8][8] = {
    {0,1,2,3,7,5,6,7},
    {1,0,3,5,4,4,2,6},
    {2,3,3,1,6,7,4,5},
    {4,2,1,0,7,6,7,4},
    {4,5,3,7,0,1,2,6},
    {5,4,7,6,1,5,5,2},
    {6,7,4,5,2,4,0,6},
    {7,6,3,4,3,3,1,5}};
__constant__ float c_sgn[8][8] = {
    { 1,-1,-1,-1,-1,-1,-1,-1},
    { 1,-1,-1, 1,-1, 1, 1,-1},
    { 1, 1, 1,-1,-1,-1, 1, 1},
    { 1,-1, 1, 1,-1,-1,-1, 1},
    { 1,-1, 1, 1, 1,-1,-1,-1},
    { 1,-1, 1,-1, 1, 1, 1,-1},
    { 1,-1,-1, 1,-1,-1, 1, 1},
    { 1, 1,-1,-1, 1, 1,-1, 1}};

// ---------------- 1) build hamilton (512x128) + zero BN stats ---------------
__global__ void build_hamilton_kernel(const float* __restrict__ w) {
    int t = blockIdx.x * blockDim.x + threadIdx.x;   // 0 .. 65535
    if (t < OUT_F) { g_colsum[t] = 0.f; g_colsumsq[t] = 0.f; }
    if (t >= IN_F * OUT_F) return;
    int r  = t >> 7;          // 0..511
    int c  = t & 127;         // 0..127
    int i  = r >> 6;          // row block
    int ri = r & 63;
    int j  = c >> 4;          // col block
    int cj = c & 15;
    int p  = c_idx[j][i];
    g_hamilton[t] = c_sgn[j][i] * w[ri * OUT_F + p * 16 + cj];
}

// ---------------- 2) SGEMM: support = input @ hamilton ----------------------
// BM=128, BN=128(=OUT_F), BK=16, 256 threads, 8x8 accumulators per thread.
__global__ __launch_bounds__(256) void gemm_kernel(const float* __restrict__ A, int M) {
    __shared__ float As[16][128];   // A tile, transposed: As[k][m]
    __shared__ float Bs[16][128];   // B tile: Bs[k][n]

    const int m0  = blockIdx.x * 128;
    const int tid = threadIdx.x;
    const int tx  = tid & 15;       // col group (8 cols each)
    const int ty  = tid >> 4;       // row group (8 rows each)

    float acc[8][8];
    #pragma unroll
    for (int i = 0; i < 8; i++)
        #pragma unroll
        for (int j = 0; j < 8; j++) acc[i][j] = 0.f;

    for (int k0 = 0; k0 < IN_F; k0 += 16) {
        // Load A tile 128x16 (512 float4), transpose into As[k][m]
        #pragma unroll
        for (int q = 0; q < 2; q++) {
            int f   = tid + q * 256;
            int row = f >> 2;
            int k4  = (f & 3) << 2;
            float4 v = make_float4(0.f, 0.f, 0.f, 0.f);
            int m = m0 + row;
            if (m < M)
                v = *(const float4*)(A + (long long)m * IN_F + k0 + k4);
            As[k4 + 0][row] = v.x;
            As[k4 + 1][row] = v.y;
            As[k4 + 2][row] = v.z;
            As[k4 + 3][row] = v.w;
        }
        // Load B tile 16x128 (512 float4)
        #pragma unroll
        for (int q = 0; q < 2; q++) {
            int f  = tid + q * 256;
            int kr = f >> 5;
            int c4 = (f & 31) << 2;
            *(float4*)&Bs[kr][c4] =
                *(const float4*)(g_hamilton + (k0 + kr) * OUT_F + c4);
        }
        __syncthreads();

        #pragma unroll
        for (int kk = 0; kk < 16; kk++) {
            float a[8], b[8];
            *(float4*)(a)     = *(float4*)&As[kk][ty * 8];
            *(float4*)(a + 4) = *(float4*)&As[kk][ty * 8 + 4];
            *(float4*)(b)     = *(float4*)&Bs[kk][tx * 8];
            *(float4*)(b + 4) = *(float4*)&Bs[kk][tx * 8 + 4];
            #pragma unroll
            for (int i = 0; i < 8; i++)
                #pragma unroll
                for (int j = 0; j < 8; j++)
                    acc[i][j] += a[i] * b[j];
        }
        __syncthreads();
    }

    // Store 8x8 per thread
    #pragma unroll
    for (int i = 0; i < 8; i++) {
        int m = m0 + ty * 8 + i;
        if (m < M) {
            float* dst = g_support + (long long)m * OUT_F + tx * 8;
            *(float4*)(dst)     = make_float4(acc[i][0], acc[i][1], acc[i][2], acc[i][3]);
            *(float4*)(dst + 4) = make_float4(acc[i][4], acc[i][5], acc[i][6], acc[i][7]);
        }
    }
}

// ---------------- 3) SpMM scatter: out[r] += v * support[c] -----------------
// One warp per edge (grid-stride); lane owns 4 consecutive features.
// red.global.add.v4.f32 = one 16B reduction per lane (sm_90+).
__global__ void spmm_kernel(const float* __restrict__ vals,
                            const int*   __restrict__ rows,
                            const int*   __restrict__ cols,
                            float* __restrict__ out, int E) {
    const int lane = threadIdx.x & 31;
    int w  = (blockIdx.x * blockDim.x + threadIdx.x) >> 5;
    int nW = (gridDim.x * blockDim.x) >> 5;
    for (int e = w; e < E; e += nW) {
        int   r = rows[e];
        int   c = cols[e];
        float v = vals[e];
        float4 s = *(const float4*)(g_support + (long long)c * OUT_F + lane * 4);
        float* dst = out + (long long)r * OUT_F + lane * 4;
        asm volatile("red.global.add.v4.f32 [%0], {%1,%2,%3,%4};"
                     :: "l"(dst), "f"(v * s.x), "f"(v * s.y),
                        "f"(v * s.z), "f"(v * s.w)
                     : "memory");
    }
}

// ---------------- 4) per-column sum / sumsq ---------------------------------
__global__ void bnstats_kernel(const float* __restrict__ out, int M) {
    const int col = threadIdx.x;      // 128 threads = 128 columns
    float s = 0.f, s2 = 0.f;
    for (int r = blockIdx.x; r < M; r += gridDim.x) {
        float v = out[(long long)r * OUT_F + col];
        s  += v;
        s2 += v * v;
    }
    atomicAdd(&g_colsum[col], s);
    atomicAdd(&g_colsumsq[col], s2);
}

// ---------------- 5) fold stats into per-column scale/shift -----------------
__global__ void bnfinal_kernel(const float* __restrict__ gamma,
                               const float* __restrict__ beta, int M) {
    int c = threadIdx.x;              // 128 threads
    float invM = 1.f / (float)M;
    float mean = g_colsum[c] * invM;
    float var  = g_colsumsq[c] * invM - mean * mean;   // biased var (ddof=0)
    float sc   = gamma[c] * rsqrtf(var + BN_EPS);
    g_scale[c] = sc;
    g_shift[c] = beta[c] - mean * sc;
}

// ---------------- 6) normalize + tanh, in place on d_out --------------------
__global__ void finalize_kernel(float* __restrict__ out, int M) {
    int idx   = blockIdx.x * blockDim.x + threadIdx.x;   // float4 index
    int total = M * (OUT_F / 4);
    if (idx >= total) return;
    int cb = (idx & 31) * 4;                             // column base
    float4 v = *(float4*)(out + (long long)idx * 4);
    v.x = tanhf(v.x * g_scale[cb + 0] + g_shift[cb + 0]);
    v.y = tanhf(v.y * g_scale[cb + 1] + g_shift[cb + 1]);
    v.z = tanhf(v.z * g_scale[cb + 2] + g_shift[cb + 2]);
    v.w = tanhf(v.w * g_scale[cb + 3] + g_shift[cb + 3]);
    *(float4*)(out + (long long)idx * 4) = v;
}

// ---------------- launch ----------------------------------------------------
extern "C" void kernel_launch(void* const* d_in, const int* in_sizes, int n_in,
                              void* d_out, int out_size) {
    const float* input  = (const float*)d_in[0];
    const float* weight = (const float*)d_in[1];
    const float* gamma  = (const float*)d_in[2];
    const float* beta   = (const float*)d_in[3];
    const float* evals  = (const float*)d_in[4];
    const int*   erows  = (const int*)d_in[5];
    const int*   ecols  = (const int*)d_in[6];
    float* out = (float*)d_out;

    const int M = in_sizes[0] / IN_F;     // 50000
    const int E = in_sizes[4];            // 500000

    cudaMemsetAsync(out, 0, (size_t)M * OUT_F * sizeof(float));
    build_hamilton_kernel<<<(IN_F * OUT_F + 255) / 256, 256>>>(weight);
    gemm_kernel<<<(M + 127) / 128, 256>>>(input, M);
    spmm_kernel<<<2048, 256>>>(evals, erows, ecols, out, E);
    bnstats_kernel<<<512, 128>>>(out, M);
    bnfinal_kernel<<<1, 128>>>(gamma, beta, M);
    finalize_kernel<<<(M * (OUT_F / 4) + 255) / 256, 256>>>(out, M);
}

// round 4
// speedup vs baseline: 1.8140x; 1.8140x over previous
#include <cuda_runtime.h>
#include <math.h>
#include <stdint.h>

#define IN_F   512
#define OUT_F  128
#define MAX_N  50000
#define BN_EPS 1e-5f

// ---------------- static device scratch (no allocations allowed) -------------
__device__ float g_hamilton[IN_F * OUT_F];                 // 256 KB (tf32-rounded)
__device__ float g_support[(long long)MAX_N * OUT_F];      // 25.6 MB
__device__ float g_colsum[OUT_F];
__device__ float g_colsumsq[OUT_F];
__device__ float g_scale[OUT_F];
__device__ float g_shift[OUT_F];

// Octonion block pattern: column-block j uses row-block list idx/sgn[j][i].
__constant__ int c_idx[8][8] = {
    {0,1,2,3,7,5,6,7},
    {1,0,3,5,4,4,2,6},
    {2,3,3,1,6,7,4,5},
    {4,2,1,0,7,6,7,4},
    {4,5,3,7,0,1,2,6},
    {5,4,7,6,1,5,5,2},
    {6,7,4,5,2,4,0,6},
    {7,6,3,4,3,3,1,5}};
__constant__ float c_sgn[8][8] = {
    { 1,-1,-1,-1,-1,-1,-1,-1},
    { 1,-1,-1, 1,-1, 1, 1,-1},
    { 1, 1, 1,-1,-1,-1, 1, 1},
    { 1,-1, 1, 1,-1,-1,-1, 1},
    { 1,-1, 1, 1, 1,-1,-1,-1},
    { 1,-1, 1,-1, 1, 1, 1,-1},
    { 1,-1,-1, 1,-1,-1, 1, 1},
    { 1, 1,-1,-1, 1, 1,-1, 1}};

__device__ __forceinline__ float to_tf32(float x) {
    uint32_t u;
    asm("cvt.rna.tf32.f32 %0, %1;" : "=r"(u) : "f"(x));
    return __uint_as_float(u);
}

__device__ __forceinline__ void mma_tf32(float c[4],
                                         uint32_t a0, uint32_t a1, uint32_t a2, uint32_t a3,
                                         uint32_t b0, uint32_t b1) {
    asm volatile(
        "mma.sync.aligned.m16n8k8.row.col.f32.tf32.tf32.f32 "
        "{%0,%1,%2,%3}, {%4,%5,%6,%7}, {%8,%9}, {%0,%1,%2,%3};"
        : "+f"(c[0]), "+f"(c[1]), "+f"(c[2]), "+f"(c[3])
        : "r"(a0), "r"(a1), "r"(a2), "r"(a3), "r"(b0), "r"(b1));
}

// ---------------- 1) build hamilton (512x128, tf32-rounded) + zero stats ----
__global__ void build_hamilton_kernel(const float* __restrict__ w) {
    int t = blockIdx.x * blockDim.x + threadIdx.x;   // 0 .. 65535
    if (t < OUT_F) { g_colsum[t] = 0.f; g_colsumsq[t] = 0.f; }
    if (t >= IN_F * OUT_F) return;
    int r  = t >> 7;          // 0..511
    int c  = t & 127;         // 0..127
    int i  = r >> 6;          // row block
    int ri = r & 63;
    int j  = c >> 4;          // col block
    int cj = c & 15;
    int p  = c_idx[j][i];
    g_hamilton[t] = to_tf32(c_sgn[j][i] * w[ri * OUT_F + p * 16 + cj]);
}

// ---------------- 2) TF32 tensor-core GEMM: support = input @ hamilton ------
// BM=128, BN=128(=OUT_F), BK=16; 256 threads = 8 warps (2 along M x 4 along N);
// warp tile 64x32 = 4x4 m16n8k8 tiles. Register-staged smem pipeline.
#define SM_STRIDE 136   // 128 + 8 pad (8*tig + g -> conflict-free frag loads)

__global__ __launch_bounds__(256) void gemm_kernel(const float* __restrict__ A, int M) {
    __shared__ float As[16][SM_STRIDE];   // [k][m], tf32-rounded
    __shared__ float Bs[16][SM_STRIDE];   // [k][n], tf32-rounded

    const int tid  = threadIdx.x;
    const int lane = tid & 31;
    const int wid  = tid >> 5;
    const int g    = lane >> 2;      // 0..7
    const int tig  = lane & 3;       // 0..3
    const int warp_m = (wid & 1) * 64;
    const int warp_n = (wid >> 1) * 32;
    const int m0 = blockIdx.x * 128;

    // staging index precompute
    const int a_row0 = (tid)       >> 2, a_k0 = ((tid)       & 3) << 2;
    const int a_row1 = (tid + 256) >> 2, a_k1 = ((tid + 256) & 3) << 2;
    const int b_kr0  = (tid)       >> 5, b_c0 = ((tid)       & 31) << 2;
    const int b_kr1  = (tid + 256) >> 5, b_c1 = ((tid + 256) & 31) << 2;

    float c[4][4][4];
    #pragma unroll
    for (int mt = 0; mt < 4; mt++)
        #pragma unroll
        for (int nt = 0; nt < 4; nt++)
            #pragma unroll
            for (int k = 0; k < 4; k++) c[mt][nt][k] = 0.f;

    float4 ar0, ar1, br0, br1;

    // prologue: load tile 0
    {
        int m = m0 + a_row0;
        ar0 = (m < M) ? *(const float4*)(A + (long long)m * IN_F + a_k0)
                      : make_float4(0.f, 0.f, 0.f, 0.f);
        m = m0 + a_row1;
        ar1 = (m < M) ? *(const float4*)(A + (long long)m * IN_F + a_k1)
                      : make_float4(0.f, 0.f, 0.f, 0.f);
        br0 = *(const float4*)(g_hamilton + b_kr0 * OUT_F + b_c0);
        br1 = *(const float4*)(g_hamilton + b_kr1 * OUT_F + b_c1);
    }
    // store tile 0
    As[a_k0 + 0][a_row0] = to_tf32(ar0.x); As[a_k0 + 1][a_row0] = to_tf32(ar0.y);
    As[a_k0 + 2][a_row0] = to_tf32(ar0.z); As[a_k0 + 3][a_row0] = to_tf32(ar0.w);
    As[a_k1 + 0][a_row1] = to_tf32(ar1.x); As[a_k1 + 1][a_row1] = to_tf32(ar1.y);
    As[a_k1 + 2][a_row1] = to_tf32(ar1.z); As[a_k1 + 3][a_row1] = to_tf32(ar1.w);
    *(float4*)&Bs[b_kr0][b_c0] = br0;
    *(float4*)&Bs[b_kr1][b_c1] = br1;
    __syncthreads();

    for (int t = 0; t < 32; t++) {
        // prefetch next tile into registers
        if (t < 31) {
            int k0 = (t + 1) * 16;
            int m = m0 + a_row0;
            ar0 = (m < M) ? *(const float4*)(A + (long long)m * IN_F + k0 + a_k0)
                          : make_float4(0.f, 0.f, 0.f, 0.f);
            m = m0 + a_row1;
            ar1 = (m < M) ? *(const float4*)(A + (long long)m * IN_F + k0 + a_k1)
                          : make_float4(0.f, 0.f, 0.f, 0.f);
            br0 = *(const float4*)(g_hamilton + (k0 + b_kr0) * OUT_F + b_c0);
            br1 = *(const float4*)(g_hamilton + (k0 + b_kr1) * OUT_F + b_c1);
        }

        // compute on current smem tile: two k-steps of 8
        #pragma unroll
        for (int s = 0; s < 2; s++) {
            uint32_t a[4][4], b[4][2];
            #pragma unroll
            for (int mt = 0; mt < 4; mt++) {
                int mm = warp_m + mt * 16 + g;
                a[mt][0] = __float_as_uint(As[s * 8 + tig    ][mm    ]);
                a[mt][1] = __float_as_uint(As[s * 8 + tig    ][mm + 8]);
                a[mt][2] = __float_as_uint(As[s * 8 + tig + 4][mm    ]);
                a[mt][3] = __float_as_uint(As[s * 8 + tig + 4][mm + 8]);
            }
            #pragma unroll
            for (int nt = 0; nt < 4; nt++) {
                int nn = warp_n + nt * 8 + g;
                b[nt][0] = __float_as_uint(Bs[s * 8 + tig    ][nn]);
                b[nt][1] = __float_as_uint(Bs[s * 8 + tig + 4][nn]);
            }
            #pragma unroll
            for (int mt = 0; mt < 4; mt++)
                #pragma unroll
                for (int nt = 0; nt < 4; nt++)
                    mma_tf32(c[mt][nt], a[mt][0], a[mt][1], a[mt][2], a[mt][3],
                             b[nt][0], b[nt][1]);
        }
        __syncthreads();
        if (t < 31) {
            As[a_k0 + 0][a_row0] = to_tf32(ar0.x); As[a_k0 + 1][a_row0] = to_tf32(ar0.y);
            As[a_k0 + 2][a_row0] = to_tf32(ar0.z); As[a_k0 + 3][a_row0] = to_tf32(ar0.w);
            As[a_k1 + 0][a_row1] = to_tf32(ar1.x); As[a_k1 + 1][a_row1] = to_tf32(ar1.y);
            As[a_k1 + 2][a_row1] = to_tf32(ar1.z); As[a_k1 + 3][a_row1] = to_tf32(ar1.w);
            *(float4*)&Bs[b_kr0][b_c0] = br0;
            *(float4*)&Bs[b_kr1][b_c1] = br1;
            __syncthreads();
        }
    }

    // epilogue: store C fragments
    #pragma unroll
    for (int mt = 0; mt < 4; mt++) {
        int r0 = m0 + warp_m + mt * 16 + g;
        int r1 = r0 + 8;
        #pragma unroll
        for (int nt = 0; nt < 4; nt++) {
            int cb = warp_n + nt * 8 + 2 * tig;
            if (r0 < M)
                *(float2*)(g_support + (long long)r0 * OUT_F + cb) =
                    make_float2(c[mt][nt][0], c[mt][nt][1]);
            if (r1 < M)
                *(float2*)(g_support + (long long)r1 * OUT_F + cb) =
                    make_float2(c[mt][nt][2], c[mt][nt][3]);
        }
    }
}

// ---------------- 3) SpMM scatter: out[r] += v * support[c] -----------------
__global__ void spmm_kernel(const float* __restrict__ vals,
                            const int*   __restrict__ rows,
                            const int*   __restrict__ cols,
                            float* __restrict__ out, int E) {
    const int lane = threadIdx.x & 31;
    int w  = (blockIdx.x * blockDim.x + threadIdx.x) >> 5;
    int nW = (gridDim.x * blockDim.x) >> 5;
    for (int e = w; e < E; e += nW) {
        int   r = rows[e];
        int   c = cols[e];
        float v = vals[e];
        float4 s = *(const float4*)(g_support + (long long)c * OUT_F + lane * 4);
        float* dst = out + (long long)r * OUT_F + lane * 4;
        asm volatile("red.global.add.v4.f32 [%0], {%1,%2,%3,%4};"
                     :: "l"(dst), "f"(v * s.x), "f"(v * s.y),
                        "f"(v * s.z), "f"(v * s.w)
                     : "memory");
    }
}

// ---------------- 4) per-column sum / sumsq (vectorized, high-MLP) ----------
__global__ __launch_bounds__(256) void bnstats_kernel(const float* __restrict__ out, int M) {
    __shared__ float4 ssum[8][32];
    __shared__ float4 ssq[8][32];
    const int tx = threadIdx.x & 31;    // column quad 0..31
    const int ty = threadIdx.x >> 5;    // warp/row-slot 0..7
    float4 s = make_float4(0.f, 0.f, 0.f, 0.f);
    float4 q = make_float4(0.f, 0.f, 0.f, 0.f);
    const int stride = gridDim.x * 8;
    #pragma unroll 4
    for (int r = blockIdx.x * 8 + ty; r < M; r += stride) {
        float4 v = *(const float4*)(out + (long long)r * OUT_F + tx * 4);
        s.x += v.x; s.y += v.y; s.z += v.z; s.w += v.w;
        q.x += v.x * v.x; q.y += v.y * v.y; q.z += v.z * v.z; q.w += v.w * v.w;
    }
    ssum[ty][tx] = s; ssq[ty][tx] = q;
    __syncthreads();
    #pragma unroll
    for (int off = 4; off > 0; off >>= 1) {
        if (ty < off) {
            float4 s2 = ssum[ty + off][tx], q2 = ssq[ty + off][tx];
            float4 sa = ssum[ty][tx],       qa = ssq[ty][tx];
            sa.x += s2.x; sa.y += s2.y; sa.z += s2.z; sa.w += s2.w;
            qa.x += q2.x; qa.y += q2.y; qa.z += q2.z; qa.w += q2.w;
            ssum[ty][tx] = sa; ssq[ty][tx] = qa;
        }
        __syncthreads();
    }
    if (ty == 0) {
        float4 sa = ssum[0][tx], qa = ssq[0][tx];
        asm volatile("red.global.add.v4.f32 [%0], {%1,%2,%3,%4};"
                     :: "l"(g_colsum + tx * 4), "f"(sa.x), "f"(sa.y), "f"(sa.z), "f"(sa.w)
                     : "memory");
        asm volatile("red.global.add.v4.f32 [%0], {%1,%2,%3,%4};"
                     :: "l"(g_colsumsq + tx * 4), "f"(qa.x), "f"(qa.y), "f"(qa.z), "f"(qa.w)
                     : "memory");
    }
}

// ---------------- 5) fold stats into per-column scale/shift -----------------
__global__ void bnfinal_kernel(const float* __restrict__ gamma,
                               const float* __restrict__ beta, int M) {
    int c = threadIdx.x;              // 128 threads
    float invM = 1.f / (float)M;
    float mean = g_colsum[c] * invM;
    float var  = g_colsumsq[c] * invM - mean * mean;   // biased var (ddof=0)
    float sc   = gamma[c] * rsqrtf(var + BN_EPS);
    g_scale[c] = sc;
    g_shift[c] = beta[c] - mean * sc;
}

// ---------------- 6) normalize + tanh, in place on d_out --------------------
__global__ void finalize_kernel(float* __restrict__ out, int M) {
    int idx   = blockIdx.x * blockDim.x + threadIdx.x;   // float4 index
    int total = M * (OUT_F / 4);
    if (idx >= total) return;
    int cb = (idx & 31) * 4;                             // column base
    float4 v = *(float4*)(out + (long long)idx * 4);
    v.x = tanhf(v.x * g_scale[cb + 0] + g_shift[cb + 0]);
    v.y = tanhf(v.y * g_scale[cb + 1] + g_shift[cb + 1]);
    v.z = tanhf(v.z * g_scale[cb + 2] + g_shift[cb + 2]);
    v.w = tanhf(v.w * g_scale[cb + 3] + g_shift[cb + 3]);
    *(float4*)(out + (long long)idx * 4) = v;
}

// ---------------- launch ----------------------------------------------------
extern "C" void kernel_launch(void* const* d_in, const int* in_sizes, int n_in,
                              void* d_out, int out_size) {
    const float* input  = (const float*)d_in[0];
    const float* weight = (const float*)d_in[1];
    const float* gamma  = (const float*)d_in[2];
    const float* beta   = (const float*)d_in[3];
    const float* evals  = (const float*)d_in[4];
    const int*   erows  = (const int*)d_in[5];
    const int*   ecols  = (const int*)d_in[6];
    float* out = (float*)d_out;

    const int M = in_sizes[0] / IN_F;     // 50000
    const int E = in_sizes[4];            // 500000

    cudaMemsetAsync(out, 0, (size_t)M * OUT_F * sizeof(float));
    build_hamilton_kernel<<<(IN_F * OUT_F + 255) / 256, 256>>>(weight);
    gemm_kernel<<<(M + 127) / 128, 256>>>(input, M);
    spmm_kernel<<<1184, 256>>>(evals, erows, ecols, out, E);
    bnstats_kernel<<<296, 256>>>(out, M);
    bnfinal_kernel<<<1, 128>>>(gamma, beta, M);
    finalize_kernel<<<(M * (OUT_F / 4) + 255) / 256, 256>>>(out, M);
}